// round 7
// baseline (speedup 1.0000x reference)
#include <cuda_runtime.h>
#include <cuda_fp16.h>
#include <math.h>
#include <stdint.h>

// ---------------------------------------------------------------------------
// Vit_Spatial_Map (sm_103 PTX target => legacy mma.sync path).
// FP16 mma.sync m16n8k16, fp32 accumulate.
// B=8, Np=1024, DIM=256, HEADS=4, DH=64, patch_dim=4096, M=8192.
//   emb  = patches @ W_embed^T + b_embed + pos        (8192 x 256, K=4096)
//   q    = emb @ Wq_avg^T (row-mean of Wq per head)   (8192 x 4)
//   k    = sigmoid(q @ Wk^T)                          (32 x 1024)
//   kv   = (emb @ Wv^T) * k                           (8192 x 256, K=256)
//   out  = fold(kv @ Wout^T + b_out)                  (8192 x 4096, K=256)
// ---------------------------------------------------------------------------

static __device__ float g_emb[8192 * 256];
static __device__ float g_kv[8192 * 256];
static __device__ float g_wqavg[4 * 256];
static __device__ float g_q[32 * 1024];
static __device__ float g_k[32 * 1024];

enum { MODE_EMBED = 0, MODE_KV = 1, MODE_OUT = 2 };

__device__ __forceinline__ uint32_t pack_h2(float x, float y) {
    const __half2 h = __floats2half2_rn(x, y);
    return *reinterpret_cast<const uint32_t*>(&h);
}
__device__ __forceinline__ void mma_f16(float* c, const uint32_t* a, const uint32_t* b) {
    asm volatile(
        "mma.sync.aligned.m16n8k16.row.col.f32.f16.f16.f32 "
        "{%0,%1,%2,%3}, {%4,%5,%6,%7}, {%8,%9}, {%0,%1,%2,%3};"
        : "+f"(c[0]), "+f"(c[1]), "+f"(c[2]), "+f"(c[3])
        : "r"(a[0]), "r"(a[1]), "r"(a[2]), "r"(a[3]), "r"(b[0]), "r"(b[1]));
}

// C(M x N) = A(M x K) * B(N x K)^T.  BM=128, BN=128, BK=32, 256 threads.
// Warp grid 4(m) x 2(n); warp tile 32 x 64 = (2 x m16) x (8 x n8), 2 k16/tile.
// SMEM halves [row][16 words], XOR swizzle word ^= (row&7)*2 (conflict-free).
template <int MODE, int K>
__global__ __launch_bounds__(256) void gemm_h(
    const float* __restrict__ Ap, const float* __restrict__ Bp,
    float* __restrict__ Cp, const float* __restrict__ bias,
    const float* __restrict__ pos)
{
    __shared__ __align__(16) uint32_t As[2][128 * 16];
    __shared__ __align__(16) uint32_t Bs[2][128 * 16];

    const int tid   = threadIdx.x;
    const int mBase = blockIdx.y * 128;
    const int nBase = blockIdx.x * 128;

    const int warp = tid >> 5;
    const int lane = tid & 31;
    const int g    = lane >> 2;
    const int tg   = lane & 3;
    const int mw   = (warp & 3) * 32;
    const int nw   = (warp >> 2) * 64;

    const float* A = (MODE == MODE_EMBED) ? Ap : (MODE == MODE_KV ? g_emb : g_kv);

    float acc[2][8][4];
#pragma unroll
    for (int i = 0; i < 2; i++)
#pragma unroll
        for (int j = 0; j < 8; j++)
#pragma unroll
            for (int l = 0; l < 4; l++) acc[i][j][l] = 0.0f;

    float4 av[4], bv[4];

    auto load_tile = [&](int kt) {
        const int kbase = kt * 32;
#pragma unroll
        for (int i = 0; i < 4; i++) {
            const int f   = tid + 256 * i;
            const int row = f >> 3;
            const int k4  = f & 7;
            const int ka  = kbase + k4 * 4;
            if (MODE == MODE_EMBED) {
                const int c  = ka >> 6;
                const int kh = (ka >> 3) & 7;
                const int kw = ka & 7;
                const int m  = mBase + row;
                const int bn = m >> 10, n = m & 1023;
                const int ph = n >> 5, pw = n & 31;
                const size_t idx =
                    ((((size_t)bn * 64 + c) * 256) + (size_t)(ph * 8 + kh)) * 256
                    + (size_t)(pw * 8 + kw);
                av[i] = *reinterpret_cast<const float4*>(A + idx);
            } else {
                av[i] = *reinterpret_cast<const float4*>(
                    A + (size_t)(mBase + row) * K + ka);
            }
            bv[i] = *reinterpret_cast<const float4*>(
                Bp + (size_t)(nBase + row) * K + ka);
        }
    };

    auto store_tile = [&](int s) {
#pragma unroll
        for (int i = 0; i < 4; i++) {
            const int f   = tid + 256 * i;
            const int row = f >> 3;
            const int k4  = f & 7;
            const int wo  = (k4 * 2) ^ ((row & 7) * 2);
            const uint2 ua = make_uint2(pack_h2(av[i].x, av[i].y),
                                        pack_h2(av[i].z, av[i].w));
            const uint2 ub = make_uint2(pack_h2(bv[i].x, bv[i].y),
                                        pack_h2(bv[i].z, bv[i].w));
            *reinterpret_cast<uint2*>(&As[s][row * 16 + wo]) = ua;
            *reinterpret_cast<uint2*>(&Bs[s][row * 16 + wo]) = ub;
        }
    };

    auto compute_tile = [&](int s) {
        const int sw = g * 2;
#pragma unroll
        for (int ks = 0; ks < 2; ks++) {
            const int w0 = (ks * 8 + tg) ^ sw;
            const int w2 = (ks * 8 + tg + 4) ^ sw;
            uint32_t a[2][4], b[8][2];
#pragma unroll
            for (int mt = 0; mt < 2; mt++) {
                const uint32_t* R0 = &As[s][(mw + mt * 16 + g) * 16];
                const uint32_t* R8 = R0 + 8 * 16;
                a[mt][0] = R0[w0];  a[mt][1] = R8[w0];
                a[mt][2] = R0[w2];  a[mt][3] = R8[w2];
            }
#pragma unroll
            for (int nt = 0; nt < 8; nt++) {
                const uint32_t* Rn = &Bs[s][(nw + nt * 8 + g) * 16];
                b[nt][0] = Rn[w0];  b[nt][1] = Rn[w2];
            }
#pragma unroll
            for (int mt = 0; mt < 2; mt++)
#pragma unroll
                for (int nt = 0; nt < 8; nt++)
                    mma_f16(acc[mt][nt], a[mt], b[nt]);
        }
    };

    constexpr int NT = K / 32;
    load_tile(0);
    store_tile(0);
    __syncthreads();

    for (int kt = 0; kt < NT; kt++) {
        const int s = kt & 1;
        if (kt + 1 < NT) load_tile(kt + 1);
        compute_tile(s);
        if (kt + 1 < NT) store_tile(1 - s);
        __syncthreads();
    }

    // ---------------- epilogue ----------------
#pragma unroll
    for (int mt = 0; mt < 2; mt++) {
#pragma unroll
        for (int half = 0; half < 2; half++) {
            const int m  = mBase + mw + mt * 16 + g + half * 8;
            const int bn = m >> 10, n = m & 1023;
            float kf;
            if (MODE == MODE_KV) {
                const int h = (nBase + nw) >> 6;  // nw multiple of 64
                kf = g_k[(bn * 4 + h) * 1024 + n];
            }
#pragma unroll
            for (int nt = 0; nt < 8; nt++) {
                const int col = nBase + nw + nt * 8 + tg * 2;
                float vx = acc[mt][nt][half * 2 + 0];
                float vy = acc[mt][nt][half * 2 + 1];

                if (MODE == MODE_EMBED) {
                    const float* pr = pos + (size_t)n * 256 + col;
                    vx += bias[col + 0] + pr[0];
                    vy += bias[col + 1] + pr[1];
                    *reinterpret_cast<float2*>(&g_emb[(size_t)m * 256 + col]) =
                        make_float2(vx, vy);
                } else if (MODE == MODE_KV) {
                    vx *= kf; vy *= kf;
                    *reinterpret_cast<float2*>(&g_kv[(size_t)m * 256 + col]) =
                        make_float2(vx, vy);
                } else {
                    vx += bias[col + 0];
                    vy += bias[col + 1];
                    const int ph = n >> 5, pw = n & 31;
                    const int c  = col >> 6;
                    const int kh = (col >> 3) & 7;
                    const int kw = col & 7;
                    const size_t idx =
                        ((((size_t)bn * 64 + c) * 256) + (size_t)(ph * 8 + kh)) * 256
                        + (size_t)(pw * 8 + kw);
                    *reinterpret_cast<float2*>(Cp + idx) = make_float2(vx, vy);
                }
            }
        }
    }
}

// Wq_avg[h][j] = mean over d of Wq[h*64+d][j]
__global__ void k_wqavg(const float* __restrict__ Wq)
{
    const int h = blockIdx.x, j = threadIdx.x;
    float s = 0.0f;
#pragma unroll 8
    for (int d = 0; d < 64; d++) s += Wq[(size_t)(h * 64 + d) * 256 + j];
    g_wqavg[h * 256 + j] = s * (1.0f / 64.0f);
}

// q: warp per emb row, all 4 heads at once (emb read exactly once).
__global__ __launch_bounds__(256) void k_q2()
{
    __shared__ float wqs[4 * 256];
    const int tid = threadIdx.x;
#pragma unroll
    for (int i = 0; i < 4; i++) wqs[i * 256 + tid] = g_wqavg[i * 256 + tid];
    __syncthreads();

    const int m    = blockIdx.x * 8 + (tid >> 5);
    const int lane = tid & 31;
    const float4* e4 = reinterpret_cast<const float4*>(g_emb + (size_t)m * 256);

    float s[4] = {0.f, 0.f, 0.f, 0.f};
#pragma unroll
    for (int part = 0; part < 2; part++) {
        const float4 ev = e4[lane + part * 32];
        const int base = part * 128 + lane * 4;
#pragma unroll
        for (int h = 0; h < 4; h++) {
            const float4 wv = *reinterpret_cast<const float4*>(&wqs[h * 256 + base]);
            s[h] += ev.x * wv.x + ev.y * wv.y + ev.z * wv.z + ev.w * wv.w;
        }
    }
#pragma unroll
    for (int h = 0; h < 4; h++)
#pragma unroll
        for (int o = 16; o > 0; o >>= 1)
            s[h] += __shfl_xor_sync(0xFFFFFFFFu, s[h], o);

    if (lane == 0) {
        const int bn = m >> 10, n = m & 1023;
#pragma unroll
        for (int h = 0; h < 4; h++)
            g_q[(bn * 4 + h) * 1024 + n] = s[h];
    }
}

// k = sigmoid(q @ Wk^T): warp per Wk row; q (128 KB) is L2-resident -> __ldg.
__global__ __launch_bounds__(256) void k_sig3(const float* __restrict__ Wk)
{
    const int m    = blockIdx.x * 8 + (threadIdx.x >> 5);
    const int lane = threadIdx.x & 31;

    float4 wr[8];
    const float4* wk4 = reinterpret_cast<const float4*>(Wk + (size_t)m * 1024);
#pragma unroll
    for (int j = 0; j < 8; j++) wr[j] = wk4[j * 32 + lane];

#pragma unroll 2
    for (int bh = 0; bh < 32; bh++) {
        const float4* q4 = reinterpret_cast<const float4*>(g_q + (size_t)bh * 1024);
        float s = 0.0f;
#pragma unroll
        for (int j = 0; j < 8; j++) {
            const float4 q = __ldg(&q4[j * 32 + lane]);
            s += q.x * wr[j].x + q.y * wr[j].y + q.z * wr[j].z + q.w * wr[j].w;
        }
#pragma unroll
        for (int o = 16; o > 0; o >>= 1) s += __shfl_xor_sync(0xFFFFFFFFu, s, o);
        if (lane == 0) g_k[bh * 1024 + m] = 1.0f / (1.0f + expf(-s));
    }
}

extern "C" void kernel_launch(void* const* d_in, const int* in_sizes, int n_in,
                              void* d_out, int out_size)
{
    const float* x    = (const float*)d_in[0];
    const float* Wemb = (const float*)d_in[1];
    const float* bemb = (const float*)d_in[2];
    const float* pos  = (const float*)d_in[3];
    const float* Wq   = (const float*)d_in[4];
    const float* Wk   = (const float*)d_in[5];
    const float* Wv   = (const float*)d_in[6];
    const float* Wout = (const float*)d_in[7];
    const float* bout = (const float*)d_in[8];
    float* out = (float*)d_out;

    k_wqavg<<<4, 256>>>(Wq);
    gemm_h<MODE_EMBED, 4096><<<dim3(2, 64), 256>>>(x, Wemb, nullptr, bemb, pos);
    k_q2<<<1024, 256>>>();
    k_sig3<<<128, 256>>>(Wk);
    gemm_h<MODE_KV, 256><<<dim3(2, 64), 256>>>(nullptr, Wv, nullptr, nullptr, nullptr);
    gemm_h<MODE_OUT, 256><<<dim3(32, 64), 256>>>(nullptr, Wout, out, bout, nullptr);
}

// round 8
// speedup vs baseline: 1.0066x; 1.0066x over previous
#include <cuda_runtime.h>
#include <cuda_fp16.h>
#include <math.h>
#include <stdint.h>

// ---------------------------------------------------------------------------
// Vit_Spatial_Map (sm_103 PTX target => legacy mma.sync path).
// FP16 mma.sync m16n8k16, fp32 accumulate.
// B=8, Np=1024, DIM=256, HEADS=4, DH=64, patch_dim=4096, M=8192.
//   emb  = patches @ W_embed^T + b_embed + pos        (8192 x 256, K=4096)
//   q    = emb @ Wq_avg^T (row-mean of Wq per head)   (8192 x 4)
//   k    = sigmoid(q @ Wk^T)                          (32 x 1024)
//   kv   = (emb @ Wv^T) * k                           (8192 x 256, K=256)
//   out  = fold(kv @ Wout^T + b_out)                  (8192 x 4096, K=256)
// ---------------------------------------------------------------------------

static __device__ float g_emb[8192 * 256];
static __device__ float g_kv[8192 * 256];
static __device__ float g_wqavg[4 * 256];
static __device__ float g_q[32 * 1024];
static __device__ float g_k[32 * 1024];

enum { MODE_EMBED = 0, MODE_KV = 1, MODE_OUT = 2 };

__device__ __forceinline__ uint32_t pack_h2(float x, float y) {
    const __half2 h = __floats2half2_rn(x, y);
    return *reinterpret_cast<const uint32_t*>(&h);
}
__device__ __forceinline__ void mma_f16(float* c, const uint32_t* a, const uint32_t* b) {
    asm volatile(
        "mma.sync.aligned.m16n8k16.row.col.f32.f16.f16.f32 "
        "{%0,%1,%2,%3}, {%4,%5,%6,%7}, {%8,%9}, {%0,%1,%2,%3};"
        : "+f"(c[0]), "+f"(c[1]), "+f"(c[2]), "+f"(c[3])
        : "r"(a[0]), "r"(a[1]), "r"(a[2]), "r"(a[3]), "r"(b[0]), "r"(b[1]));
}

// C(M x N) = A(M x K) * B(N x K)^T.  BM=128, BN=128, BK=32, 256 threads.
// Warp grid 4(m) x 2(n); warp tile 32 x 64 = (2 x m16) x (8 x n8), 2 k16/tile.
// SMEM halves [row][16 words], XOR swizzle word ^= (row&7)*2 (conflict-free).
template <int MODE, int K>
__global__ __launch_bounds__(256) void gemm_h(
    const float* __restrict__ Ap, const float* __restrict__ Bp,
    float* __restrict__ Cp, const float* __restrict__ bias,
    const float* __restrict__ pos)
{
    __shared__ __align__(16) uint32_t As[2][128 * 16];
    __shared__ __align__(16) uint32_t Bs[2][128 * 16];

    const int tid   = threadIdx.x;
    const int mBase = blockIdx.y * 128;
    const int nBase = blockIdx.x * 128;

    const int warp = tid >> 5;
    const int lane = tid & 31;
    const int g    = lane >> 2;
    const int tg   = lane & 3;
    const int mw   = (warp & 3) * 32;
    const int nw   = (warp >> 2) * 64;

    const float* A = (MODE == MODE_EMBED) ? Ap : (MODE == MODE_KV ? g_emb : g_kv);

    float acc[2][8][4];
#pragma unroll
    for (int i = 0; i < 2; i++)
#pragma unroll
        for (int j = 0; j < 8; j++)
#pragma unroll
            for (int l = 0; l < 4; l++) acc[i][j][l] = 0.0f;

    float4 av[4], bv[4];

    auto load_tile = [&](int kt) {
        const int kbase = kt * 32;
#pragma unroll
        for (int i = 0; i < 4; i++) {
            const int f   = tid + 256 * i;
            const int row = f >> 3;
            const int k4  = f & 7;
            const int ka  = kbase + k4 * 4;
            if (MODE == MODE_EMBED) {
                const int c  = ka >> 6;
                const int kh = (ka >> 3) & 7;
                const int kw = ka & 7;
                const int m  = mBase + row;
                const int bn = m >> 10, n = m & 1023;
                const int ph = n >> 5, pw = n & 31;
                const size_t idx =
                    ((((size_t)bn * 64 + c) * 256) + (size_t)(ph * 8 + kh)) * 256
                    + (size_t)(pw * 8 + kw);
                av[i] = *reinterpret_cast<const float4*>(A + idx);
            } else {
                av[i] = *reinterpret_cast<const float4*>(
                    A + (size_t)(mBase + row) * K + ka);
            }
            bv[i] = *reinterpret_cast<const float4*>(
                Bp + (size_t)(nBase + row) * K + ka);
        }
    };

    auto store_tile = [&](int s) {
#pragma unroll
        for (int i = 0; i < 4; i++) {
            const int f   = tid + 256 * i;
            const int row = f >> 3;
            const int k4  = f & 7;
            const int wo  = (k4 * 2) ^ ((row & 7) * 2);
            const uint2 ua = make_uint2(pack_h2(av[i].x, av[i].y),
                                        pack_h2(av[i].z, av[i].w));
            const uint2 ub = make_uint2(pack_h2(bv[i].x, bv[i].y),
                                        pack_h2(bv[i].z, bv[i].w));
            *reinterpret_cast<uint2*>(&As[s][row * 16 + wo]) = ua;
            *reinterpret_cast<uint2*>(&Bs[s][row * 16 + wo]) = ub;
        }
    };

    auto compute_tile = [&](int s) {
        const int sw = g * 2;
#pragma unroll
        for (int ks = 0; ks < 2; ks++) {
            const int w0 = (ks * 8 + tg) ^ sw;
            const int w2 = (ks * 8 + tg + 4) ^ sw;
            uint32_t a[2][4], b[8][2];
#pragma unroll
            for (int mt = 0; mt < 2; mt++) {
                const uint32_t* R0 = &As[s][(mw + mt * 16 + g) * 16];
                const uint32_t* R8 = R0 + 8 * 16;
                a[mt][0] = R0[w0];  a[mt][1] = R8[w0];
                a[mt][2] = R0[w2];  a[mt][3] = R8[w2];
            }
#pragma unroll
            for (int nt = 0; nt < 8; nt++) {
                const uint32_t* Rn = &Bs[s][(nw + nt * 8 + g) * 16];
                b[nt][0] = Rn[w0];  b[nt][1] = Rn[w2];
            }
#pragma unroll
            for (int mt = 0; mt < 2; mt++)
#pragma unroll
                for (int nt = 0; nt < 8; nt++)
                    mma_f16(acc[mt][nt], a[mt], b[nt]);
        }
    };

    constexpr int NT = K / 32;
    load_tile(0);
    store_tile(0);
    __syncthreads();

    for (int kt = 0; kt < NT; kt++) {
        const int s = kt & 1;
        if (kt + 1 < NT) load_tile(kt + 1);
        compute_tile(s);
        if (kt + 1 < NT) store_tile(1 - s);
        __syncthreads();
    }

    // ---------------- epilogue ----------------
#pragma unroll
    for (int mt = 0; mt < 2; mt++) {
#pragma unroll
        for (int half = 0; half < 2; half++) {
            const int m  = mBase + mw + mt * 16 + g + half * 8;
            const int bn = m >> 10, n = m & 1023;
            float kf;
            if (MODE == MODE_KV) {
                const int h = (nBase + nw) >> 6;  // nw multiple of 64
                kf = g_k[(bn * 4 + h) * 1024 + n];
            }
#pragma unroll
            for (int nt = 0; nt < 8; nt++) {
                const int col = nBase + nw + nt * 8 + tg * 2;
                float vx = acc[mt][nt][half * 2 + 0];
                float vy = acc[mt][nt][half * 2 + 1];

                if (MODE == MODE_EMBED) {
                    const float* pr = pos + (size_t)n * 256 + col;
                    vx += bias[col + 0] + pr[0];
                    vy += bias[col + 1] + pr[1];
                    *reinterpret_cast<float2*>(&g_emb[(size_t)m * 256 + col]) =
                        make_float2(vx, vy);
                } else if (MODE == MODE_KV) {
                    vx *= kf; vy *= kf;
                    *reinterpret_cast<float2*>(&g_kv[(size_t)m * 256 + col]) =
                        make_float2(vx, vy);
                } else {
                    vx += bias[col + 0];
                    vy += bias[col + 1];
                    const int ph = n >> 5, pw = n & 31;
                    const int c  = col >> 6;
                    const int kh = (col >> 3) & 7;
                    const int kw = col & 7;
                    const size_t idx =
                        ((((size_t)bn * 64 + c) * 256) + (size_t)(ph * 8 + kh)) * 256
                        + (size_t)(pw * 8 + kw);
                    *reinterpret_cast<float2*>(Cp + idx) = make_float2(vx, vy);
                }
            }
        }
    }
}

// Wq_avg[h][j] = mean over d of Wq[h*64+d][j]
__global__ void k_wqavg(const float* __restrict__ Wq)
{
    const int h = blockIdx.x, j = threadIdx.x;
    float s = 0.0f;
#pragma unroll 8
    for (int d = 0; d < 64; d++) s += Wq[(size_t)(h * 64 + d) * 256 + j];
    g_wqavg[h * 256 + j] = s * (1.0f / 64.0f);
}

// q: warp per emb row, all 4 heads at once (emb read exactly once).
__global__ __launch_bounds__(256) void k_q2()
{
    __shared__ float wqs[4 * 256];
    const int tid = threadIdx.x;
#pragma unroll
    for (int i = 0; i < 4; i++) wqs[i * 256 + tid] = g_wqavg[i * 256 + tid];
    __syncthreads();

    const int m    = blockIdx.x * 8 + (tid >> 5);
    const int lane = tid & 31;
    const float4* e4 = reinterpret_cast<const float4*>(g_emb + (size_t)m * 256);

    float s[4] = {0.f, 0.f, 0.f, 0.f};
#pragma unroll
    for (int part = 0; part < 2; part++) {
        const float4 ev = e4[lane + part * 32];
        const int base = part * 128 + lane * 4;
#pragma unroll
        for (int h = 0; h < 4; h++) {
            const float4 wv = *reinterpret_cast<const float4*>(&wqs[h * 256 + base]);
            s[h] += ev.x * wv.x + ev.y * wv.y + ev.z * wv.z + ev.w * wv.w;
        }
    }
#pragma unroll
    for (int h = 0; h < 4; h++)
#pragma unroll
        for (int o = 16; o > 0; o >>= 1)
            s[h] += __shfl_xor_sync(0xFFFFFFFFu, s[h], o);

    if (lane == 0) {
        const int bn = m >> 10, n = m & 1023;
#pragma unroll
        for (int h = 0; h < 4; h++)
            g_q[(bn * 4 + h) * 1024 + n] = s[h];
    }
}

// k = sigmoid(q @ Wk^T).
// Warp per m: Wk row in regs (read once). bh loop chunked by 4 with 4
// independent accumulators (ILP); all warps in a block stream identical q
// addresses in identical order -> L1 broadcast reuse (q L2 traffic ~16MB).
__global__ __launch_bounds__(256) void k_sig5(const float* __restrict__ Wk)
{
    const int m    = blockIdx.x * 8 + (threadIdx.x >> 5);
    const int lane = threadIdx.x & 31;

    float4 wr[8];
    const float4* wk4 = reinterpret_cast<const float4*>(Wk + (size_t)m * 1024);
#pragma unroll
    for (int j = 0; j < 8; j++) wr[j] = wk4[j * 32 + lane];

#pragma unroll
    for (int bh0 = 0; bh0 < 32; bh0 += 4) {
        const float4* q0 = reinterpret_cast<const float4*>(g_q + (size_t)(bh0 + 0) * 1024);
        const float4* q1 = reinterpret_cast<const float4*>(g_q + (size_t)(bh0 + 1) * 1024);
        const float4* q2 = reinterpret_cast<const float4*>(g_q + (size_t)(bh0 + 2) * 1024);
        const float4* q3 = reinterpret_cast<const float4*>(g_q + (size_t)(bh0 + 3) * 1024);
        float s0 = 0.f, s1 = 0.f, s2 = 0.f, s3 = 0.f;
#pragma unroll
        for (int j = 0; j < 8; j++) {
            const int idx = j * 32 + lane;
            const float4 a0 = __ldg(&q0[idx]);
            const float4 a1 = __ldg(&q1[idx]);
            const float4 a2 = __ldg(&q2[idx]);
            const float4 a3 = __ldg(&q3[idx]);
            const float4 w = wr[j];
            s0 += a0.x * w.x + a0.y * w.y + a0.z * w.z + a0.w * w.w;
            s1 += a1.x * w.x + a1.y * w.y + a1.z * w.z + a1.w * w.w;
            s2 += a2.x * w.x + a2.y * w.y + a2.z * w.z + a2.w * w.w;
            s3 += a3.x * w.x + a3.y * w.y + a3.z * w.z + a3.w * w.w;
        }
#pragma unroll
        for (int o = 16; o > 0; o >>= 1) {
            s0 += __shfl_xor_sync(0xFFFFFFFFu, s0, o);
            s1 += __shfl_xor_sync(0xFFFFFFFFu, s1, o);
            s2 += __shfl_xor_sync(0xFFFFFFFFu, s2, o);
            s3 += __shfl_xor_sync(0xFFFFFFFFu, s3, o);
        }
        if (lane == 0) {
            g_k[(bh0 + 0) * 1024 + m] = 1.0f / (1.0f + expf(-s0));
            g_k[(bh0 + 1) * 1024 + m] = 1.0f / (1.0f + expf(-s1));
            g_k[(bh0 + 2) * 1024 + m] = 1.0f / (1.0f + expf(-s2));
            g_k[(bh0 + 3) * 1024 + m] = 1.0f / (1.0f + expf(-s3));
        }
    }
}

extern "C" void kernel_launch(void* const* d_in, const int* in_sizes, int n_in,
                              void* d_out, int out_size)
{
    const float* x    = (const float*)d_in[0];
    const float* Wemb = (const float*)d_in[1];
    const float* bemb = (const float*)d_in[2];
    const float* pos  = (const float*)d_in[3];
    const float* Wq   = (const float*)d_in[4];
    const float* Wk   = (const float*)d_in[5];
    const float* Wv   = (const float*)d_in[6];
    const float* Wout = (const float*)d_in[7];
    const float* bout = (const float*)d_in[8];
    float* out = (float*)d_out;

    k_wqavg<<<4, 256>>>(Wq);
    gemm_h<MODE_EMBED, 4096><<<dim3(2, 64), 256>>>(x, Wemb, nullptr, bemb, pos);
    k_q2<<<1024, 256>>>();
    k_sig5<<<128, 256>>>(Wk);
    gemm_h<MODE_KV, 256><<<dim3(2, 64), 256>>>(nullptr, Wv, nullptr, nullptr, nullptr);
    gemm_h<MODE_OUT, 256><<<dim3(32, 64), 256>>>(nullptr, Wout, out, bout, nullptr);
}

// round 9
// speedup vs baseline: 1.0330x; 1.0263x over previous
#include <cuda_runtime.h>
#include <cuda_fp16.h>
#include <math.h>
#include <stdint.h>

// ---------------------------------------------------------------------------
// Vit_Spatial_Map (sm_103 PTX target => legacy mma.sync path).
// FP16 mma.sync m16n8k16, fp32 accumulate.
// B=8, Np=1024, DIM=256, HEADS=4, DH=64, patch_dim=4096, M=8192.
//   emb  = patches @ W_embed^T + b_embed + pos        (8192 x 256, K=4096)
//   q    = emb @ Wq_avg^T (row-mean of Wq per head)   (8192 x 4)
//   k    = sigmoid(q @ Wk^T)                          (32 x 1024)
//   kv   = (emb @ Wv^T) * k                           (8192 x 256, K=256)
//   out  = fold(kv @ Wout^T + b_out)                  (8192 x 4096, K=256)
// ---------------------------------------------------------------------------

static __device__ float g_emb[8192 * 256];
static __device__ float g_kv[8192 * 256];
static __device__ float g_wqavg[4 * 256];
static __device__ float g_q[32 * 1024];
static __device__ float g_k[32 * 1024];

enum { MODE_EMBED = 0, MODE_KV = 1, MODE_OUT = 2 };

__device__ __forceinline__ uint32_t pack_h2(float x, float y) {
    const __half2 h = __floats2half2_rn(x, y);
    return *reinterpret_cast<const uint32_t*>(&h);
}
__device__ __forceinline__ void mma_f16(float* c, const uint32_t* a, const uint32_t* b) {
    asm volatile(
        "mma.sync.aligned.m16n8k16.row.col.f32.f16.f16.f32 "
        "{%0,%1,%2,%3}, {%4,%5,%6,%7}, {%8,%9}, {%0,%1,%2,%3};"
        : "+f"(c[0]), "+f"(c[1]), "+f"(c[2]), "+f"(c[3])
        : "r"(a[0]), "r"(a[1]), "r"(a[2]), "r"(a[3]), "r"(b[0]), "r"(b[1]));
}

// C(M x N) = A(M x K) * B(N x K)^T.  BM=128, BN=128, BK=32, 256 threads.
// Warp grid 4(m) x 2(n); warp tile 32 x 64 = (2 x m16) x (8 x n8), 2 k16/tile.
// SMEM halves [row][16 words], XOR swizzle word ^= (row&7)*2 (conflict-free).
template <int MODE, int K>
__global__ __launch_bounds__(256) void gemm_h(
    const float* __restrict__ Ap, const float* __restrict__ Bp,
    float* __restrict__ Cp, const float* __restrict__ bias,
    const float* __restrict__ pos)
{
    __shared__ __align__(16) uint32_t As[2][128 * 16];
    __shared__ __align__(16) uint32_t Bs[2][128 * 16];

    const int tid   = threadIdx.x;
    const int mBase = blockIdx.y * 128;
    const int nBase = blockIdx.x * 128;

    const int warp = tid >> 5;
    const int lane = tid & 31;
    const int g    = lane >> 2;
    const int tg   = lane & 3;
    const int mw   = (warp & 3) * 32;
    const int nw   = (warp >> 2) * 64;

    const float* A = (MODE == MODE_EMBED) ? Ap : (MODE == MODE_KV ? g_emb : g_kv);

    float acc[2][8][4];
#pragma unroll
    for (int i = 0; i < 2; i++)
#pragma unroll
        for (int j = 0; j < 8; j++)
#pragma unroll
            for (int l = 0; l < 4; l++) acc[i][j][l] = 0.0f;

    float4 av[4], bv[4];

    auto load_tile = [&](int kt) {
        const int kbase = kt * 32;
#pragma unroll
        for (int i = 0; i < 4; i++) {
            const int f   = tid + 256 * i;
            const int row = f >> 3;
            const int k4  = f & 7;
            const int ka  = kbase + k4 * 4;
            if (MODE == MODE_EMBED) {
                const int c  = ka >> 6;
                const int kh = (ka >> 3) & 7;
                const int kw = ka & 7;
                const int m  = mBase + row;
                const int bn = m >> 10, n = m & 1023;
                const int ph = n >> 5, pw = n & 31;
                const size_t idx =
                    ((((size_t)bn * 64 + c) * 256) + (size_t)(ph * 8 + kh)) * 256
                    + (size_t)(pw * 8 + kw);
                av[i] = *reinterpret_cast<const float4*>(A + idx);
            } else {
                av[i] = *reinterpret_cast<const float4*>(
                    A + (size_t)(mBase + row) * K + ka);
            }
            bv[i] = *reinterpret_cast<const float4*>(
                Bp + (size_t)(nBase + row) * K + ka);
        }
    };

    auto store_tile = [&](int s) {
#pragma unroll
        for (int i = 0; i < 4; i++) {
            const int f   = tid + 256 * i;
            const int row = f >> 3;
            const int k4  = f & 7;
            const int wo  = (k4 * 2) ^ ((row & 7) * 2);
            const uint2 ua = make_uint2(pack_h2(av[i].x, av[i].y),
                                        pack_h2(av[i].z, av[i].w));
            const uint2 ub = make_uint2(pack_h2(bv[i].x, bv[i].y),
                                        pack_h2(bv[i].z, bv[i].w));
            *reinterpret_cast<uint2*>(&As[s][row * 16 + wo]) = ua;
            *reinterpret_cast<uint2*>(&Bs[s][row * 16 + wo]) = ub;
        }
    };

    auto compute_tile = [&](int s) {
        const int sw = g * 2;
#pragma unroll
        for (int ks = 0; ks < 2; ks++) {
            const int w0 = (ks * 8 + tg) ^ sw;
            const int w2 = (ks * 8 + tg + 4) ^ sw;
            uint32_t a[2][4], b[8][2];
#pragma unroll
            for (int mt = 0; mt < 2; mt++) {
                const uint32_t* R0 = &As[s][(mw + mt * 16 + g) * 16];
                const uint32_t* R8 = R0 + 8 * 16;
                a[mt][0] = R0[w0];  a[mt][1] = R8[w0];
                a[mt][2] = R0[w2];  a[mt][3] = R8[w2];
            }
#pragma unroll
            for (int nt = 0; nt < 8; nt++) {
                const uint32_t* Rn = &Bs[s][(nw + nt * 8 + g) * 16];
                b[nt][0] = Rn[w0];  b[nt][1] = Rn[w2];
            }
#pragma unroll
            for (int mt = 0; mt < 2; mt++)
#pragma unroll
                for (int nt = 0; nt < 8; nt++)
                    mma_f16(acc[mt][nt], a[mt], b[nt]);
        }
    };

    constexpr int NT = K / 32;
    load_tile(0);
    store_tile(0);
    __syncthreads();

    for (int kt = 0; kt < NT; kt++) {
        const int s = kt & 1;
        if (kt + 1 < NT) load_tile(kt + 1);
        compute_tile(s);
        if (kt + 1 < NT) store_tile(1 - s);
        __syncthreads();
    }

    // ---------------- epilogue ----------------
#pragma unroll
    for (int mt = 0; mt < 2; mt++) {
#pragma unroll
        for (int half = 0; half < 2; half++) {
            const int m  = mBase + mw + mt * 16 + g + half * 8;
            const int bn = m >> 10, n = m & 1023;
            float kf;
            if (MODE == MODE_KV) {
                const int h = (nBase + nw) >> 6;  // nw multiple of 64
                kf = g_k[(bn * 4 + h) * 1024 + n];
            }
#pragma unroll
            for (int nt = 0; nt < 8; nt++) {
                const int col = nBase + nw + nt * 8 + tg * 2;
                float vx = acc[mt][nt][half * 2 + 0];
                float vy = acc[mt][nt][half * 2 + 1];

                if (MODE == MODE_EMBED) {
                    const float* pr = pos + (size_t)n * 256 + col;
                    vx += bias[col + 0] + pr[0];
                    vy += bias[col + 1] + pr[1];
                    *reinterpret_cast<float2*>(&g_emb[(size_t)m * 256 + col]) =
                        make_float2(vx, vy);
                } else if (MODE == MODE_KV) {
                    vx *= kf; vy *= kf;
                    *reinterpret_cast<float2*>(&g_kv[(size_t)m * 256 + col]) =
                        make_float2(vx, vy);
                } else {
                    vx += bias[col + 0];
                    vy += bias[col + 1];
                    const int ph = n >> 5, pw = n & 31;
                    const int c  = col >> 6;
                    const int kh = (col >> 3) & 7;
                    const int kw = col & 7;
                    const size_t idx =
                        ((((size_t)bn * 64 + c) * 256) + (size_t)(ph * 8 + kh)) * 256
                        + (size_t)(pw * 8 + kw);
                    *reinterpret_cast<float2*>(Cp + idx) = make_float2(vx, vy);
                }
            }
        }
    }
}

// Wq_avg[h][j] = mean over d of Wq[h*64+d][j]
__global__ void k_wqavg(const float* __restrict__ Wq)
{
    const int h = blockIdx.x, j = threadIdx.x;
    float s = 0.0f;
#pragma unroll 8
    for (int d = 0; d < 64; d++) s += Wq[(size_t)(h * 64 + d) * 256 + j];
    g_wqavg[h * 256 + j] = s * (1.0f / 64.0f);
}

// q: warp per emb row, all 4 heads at once (emb read exactly once).
__global__ __launch_bounds__(256) void k_q2()
{
    __shared__ float wqs[4 * 256];
    const int tid = threadIdx.x;
#pragma unroll
    for (int i = 0; i < 4; i++) wqs[i * 256 + tid] = g_wqavg[i * 256 + tid];
    __syncthreads();

    const int m    = blockIdx.x * 8 + (tid >> 5);
    const int lane = tid & 31;
    const float4* e4 = reinterpret_cast<const float4*>(g_emb + (size_t)m * 256);

    float s[4] = {0.f, 0.f, 0.f, 0.f};
#pragma unroll
    for (int part = 0; part < 2; part++) {
        const float4 ev = e4[lane + part * 32];
        const int base = part * 128 + lane * 4;
#pragma unroll
        for (int h = 0; h < 4; h++) {
            const float4 wv = *reinterpret_cast<const float4*>(&wqs[h * 256 + base]);
            s[h] += ev.x * wv.x + ev.y * wv.y + ev.z * wv.z + ev.w * wv.w;
        }
    }
#pragma unroll
    for (int h = 0; h < 4; h++)
#pragma unroll
        for (int o = 16; o > 0; o >>= 1)
            s[h] += __shfl_xor_sync(0xFFFFFFFFu, s[h], o);

    if (lane == 0) {
        const int bn = m >> 10, n = m & 1023;
#pragma unroll
        for (int h = 0; h < 4; h++)
            g_q[(bn * 4 + h) * 1024 + n] = s[h];
    }
}

// k = sigmoid(q @ Wk^T).
// Grid (128, 8): block = 8 m-rows x 4 bh. Warp per m: Wk row in regs,
// 4 bh accumulated in parallel (ILP), 8x the occupancy of the 1D version.
__global__ __launch_bounds__(256) void k_sig6(const float* __restrict__ Wk)
{
    const int m    = blockIdx.x * 8 + (threadIdx.x >> 5);
    const int bh0  = blockIdx.y * 4;
    const int lane = threadIdx.x & 31;

    float4 wr[8];
    const float4* wk4 = reinterpret_cast<const float4*>(Wk + (size_t)m * 1024);
#pragma unroll
    for (int j = 0; j < 8; j++) wr[j] = wk4[j * 32 + lane];

    const float4* q0 = reinterpret_cast<const float4*>(g_q + (size_t)(bh0 + 0) * 1024);
    const float4* q1 = reinterpret_cast<const float4*>(g_q + (size_t)(bh0 + 1) * 1024);
    const float4* q2 = reinterpret_cast<const float4*>(g_q + (size_t)(bh0 + 2) * 1024);
    const float4* q3 = reinterpret_cast<const float4*>(g_q + (size_t)(bh0 + 3) * 1024);
    float s0 = 0.f, s1 = 0.f, s2 = 0.f, s3 = 0.f;
#pragma unroll
    for (int j = 0; j < 8; j++) {
        const int idx = j * 32 + lane;
        const float4 a0 = __ldg(&q0[idx]);
        const float4 a1 = __ldg(&q1[idx]);
        const float4 a2 = __ldg(&q2[idx]);
        const float4 a3 = __ldg(&q3[idx]);
        const float4 w = wr[j];
        s0 += a0.x * w.x + a0.y * w.y + a0.z * w.z + a0.w * w.w;
        s1 += a1.x * w.x + a1.y * w.y + a1.z * w.z + a1.w * w.w;
        s2 += a2.x * w.x + a2.y * w.y + a2.z * w.z + a2.w * w.w;
        s3 += a3.x * w.x + a3.y * w.y + a3.z * w.z + a3.w * w.w;
    }
#pragma unroll
    for (int o = 16; o > 0; o >>= 1) {
        s0 += __shfl_xor_sync(0xFFFFFFFFu, s0, o);
        s1 += __shfl_xor_sync(0xFFFFFFFFu, s1, o);
        s2 += __shfl_xor_sync(0xFFFFFFFFu, s2, o);
        s3 += __shfl_xor_sync(0xFFFFFFFFu, s3, o);
    }
    if (lane == 0) {
        g_k[(bh0 + 0) * 1024 + m] = 1.0f / (1.0f + expf(-s0));
        g_k[(bh0 + 1) * 1024 + m] = 1.0f / (1.0f + expf(-s1));
        g_k[(bh0 + 2) * 1024 + m] = 1.0f / (1.0f + expf(-s2));
        g_k[(bh0 + 3) * 1024 + m] = 1.0f / (1.0f + expf(-s3));
    }
}

extern "C" void kernel_launch(void* const* d_in, const int* in_sizes, int n_in,
                              void* d_out, int out_size)
{
    const float* x    = (const float*)d_in[0];
    const float* Wemb = (const float*)d_in[1];
    const float* bemb = (const float*)d_in[2];
    const float* pos  = (const float*)d_in[3];
    const float* Wq   = (const float*)d_in[4];
    const float* Wk   = (const float*)d_in[5];
    const float* Wv   = (const float*)d_in[6];
    const float* Wout = (const float*)d_in[7];
    const float* bout = (const float*)d_in[8];
    float* out = (float*)d_out;

    k_wqavg<<<4, 256>>>(Wq);
    gemm_h<MODE_EMBED, 4096><<<dim3(2, 64), 256>>>(x, Wemb, nullptr, bemb, pos);
    k_q2<<<1024, 256>>>();
    k_sig6<<<dim3(128, 8), 256>>>(Wk);
    gemm_h<MODE_KV, 256><<<dim3(2, 64), 256>>>(nullptr, Wv, nullptr, nullptr, nullptr);
    gemm_h<MODE_OUT, 256><<<dim3(32, 64), 256>>>(nullptr, Wout, out, bout, nullptr);
}

// round 10
// speedup vs baseline: 1.0834x; 1.0488x over previous
#include <cuda_runtime.h>
#include <cuda_fp16.h>
#include <math.h>
#include <stdint.h>

// ---------------------------------------------------------------------------
// Vit_Spatial_Map (sm_103 PTX target => legacy mma.sync path).
// FP16 mma.sync m16n8k16, fp32 accumulate.
// B=8, Np=1024, DIM=256, HEADS=4, DH=64, patch_dim=4096, M=8192.
//   emb  = patches @ W_embed^T + b_embed + pos        (8192 x 256, K=4096)
//   q    = emb @ Wq_avg^T (row-mean of Wq per head)   (8192 x 4)
//   k    = sigmoid(q @ Wk^T)                          (32 x 1024)
//   kv   = (emb @ Wv^T) * k                           (8192 x 256, K=256)
//   out  = fold(kv @ Wout^T + b_out)                  (8192 x 4096, K=256)
// ---------------------------------------------------------------------------

static __device__ float g_emb[8192 * 256];
static __device__ float g_kv[8192 * 256];
static __device__ float g_wqavg[4 * 256];
static __device__ float g_q[32 * 1024];
static __device__ float g_k[32 * 1024];

enum { MODE_EMBED = 0, MODE_KV = 1, MODE_OUT = 2 };

__device__ __forceinline__ uint32_t pack_h2(float x, float y) {
    const __half2 h = __floats2half2_rn(x, y);
    return *reinterpret_cast<const uint32_t*>(&h);
}
__device__ __forceinline__ void mma_f16(float* c, const uint32_t* a, const uint32_t* b) {
    asm volatile(
        "mma.sync.aligned.m16n8k16.row.col.f32.f16.f16.f32 "
        "{%0,%1,%2,%3}, {%4,%5,%6,%7}, {%8,%9}, {%0,%1,%2,%3};"
        : "+f"(c[0]), "+f"(c[1]), "+f"(c[2]), "+f"(c[3])
        : "r"(a[0]), "r"(a[1]), "r"(a[2]), "r"(a[3]), "r"(b[0]), "r"(b[1]));
}

// ======================= embed GEMM (BM=128, proven) ========================
// C(M x N) = A(M x K) * B(N x K)^T.  BM=128, BN=128, BK=32, 256 threads.
template <int K>
__global__ __launch_bounds__(256) void gemm_h(
    const float* __restrict__ Ap, const float* __restrict__ Bp,
    const float* __restrict__ bias, const float* __restrict__ pos)
{
    __shared__ __align__(16) uint32_t As[2][128 * 16];
    __shared__ __align__(16) uint32_t Bs[2][128 * 16];

    const int tid   = threadIdx.x;
    const int mBase = blockIdx.y * 128;
    const int nBase = blockIdx.x * 128;

    const int warp = tid >> 5;
    const int lane = tid & 31;
    const int g    = lane >> 2;
    const int tg   = lane & 3;
    const int mw   = (warp & 3) * 32;
    const int nw   = (warp >> 2) * 64;

    float acc[2][8][4];
#pragma unroll
    for (int i = 0; i < 2; i++)
#pragma unroll
        for (int j = 0; j < 8; j++)
#pragma unroll
            for (int l = 0; l < 4; l++) acc[i][j][l] = 0.0f;

    float4 av[4], bv[4];

    auto load_tile = [&](int kt) {
        const int kbase = kt * 32;
#pragma unroll
        for (int i = 0; i < 4; i++) {
            const int f   = tid + 256 * i;
            const int row = f >> 3;
            const int k4  = f & 7;
            const int ka  = kbase + k4 * 4;
            const int c  = ka >> 6;
            const int kh = (ka >> 3) & 7;
            const int kw = ka & 7;
            const int m  = mBase + row;
            const int bn = m >> 10, n = m & 1023;
            const int ph = n >> 5, pw = n & 31;
            const size_t idx =
                ((((size_t)bn * 64 + c) * 256) + (size_t)(ph * 8 + kh)) * 256
                + (size_t)(pw * 8 + kw);
            av[i] = *reinterpret_cast<const float4*>(Ap + idx);
            bv[i] = *reinterpret_cast<const float4*>(
                Bp + (size_t)(nBase + row) * K + ka);
        }
    };

    auto store_tile = [&](int s) {
#pragma unroll
        for (int i = 0; i < 4; i++) {
            const int f   = tid + 256 * i;
            const int row = f >> 3;
            const int k4  = f & 7;
            const int wo  = (k4 * 2) ^ ((row & 7) * 2);
            const uint2 ua = make_uint2(pack_h2(av[i].x, av[i].y),
                                        pack_h2(av[i].z, av[i].w));
            const uint2 ub = make_uint2(pack_h2(bv[i].x, bv[i].y),
                                        pack_h2(bv[i].z, bv[i].w));
            *reinterpret_cast<uint2*>(&As[s][row * 16 + wo]) = ua;
            *reinterpret_cast<uint2*>(&Bs[s][row * 16 + wo]) = ub;
        }
    };

    auto compute_tile = [&](int s) {
        const int sw = g * 2;
#pragma unroll
        for (int ks = 0; ks < 2; ks++) {
            const int w0 = (ks * 8 + tg) ^ sw;
            const int w2 = (ks * 8 + tg + 4) ^ sw;
            uint32_t a[2][4], b[8][2];
#pragma unroll
            for (int mt = 0; mt < 2; mt++) {
                const uint32_t* R0 = &As[s][(mw + mt * 16 + g) * 16];
                const uint32_t* R8 = R0 + 8 * 16;
                a[mt][0] = R0[w0];  a[mt][1] = R8[w0];
                a[mt][2] = R0[w2];  a[mt][3] = R8[w2];
            }
#pragma unroll
            for (int nt = 0; nt < 8; nt++) {
                const uint32_t* Rn = &Bs[s][(nw + nt * 8 + g) * 16];
                b[nt][0] = Rn[w0];  b[nt][1] = Rn[w2];
            }
#pragma unroll
            for (int mt = 0; mt < 2; mt++)
#pragma unroll
                for (int nt = 0; nt < 8; nt++)
                    mma_f16(acc[mt][nt], a[mt], b[nt]);
        }
    };

    constexpr int NT = K / 32;
    load_tile(0);
    store_tile(0);
    __syncthreads();

    for (int kt = 0; kt < NT; kt++) {
        const int s = kt & 1;
        if (kt + 1 < NT) load_tile(kt + 1);
        compute_tile(s);
        if (kt + 1 < NT) store_tile(1 - s);
        __syncthreads();
    }

#pragma unroll
    for (int mt = 0; mt < 2; mt++) {
#pragma unroll
        for (int half = 0; half < 2; half++) {
            const int m = mBase + mw + mt * 16 + g + half * 8;
            const int n = m & 1023;
#pragma unroll
            for (int nt = 0; nt < 8; nt++) {
                const int col = nBase + nw + nt * 8 + tg * 2;
                const float* pr = pos + (size_t)n * 256 + col;
                float vx = acc[mt][nt][half * 2 + 0] + bias[col + 0] + pr[0];
                float vy = acc[mt][nt][half * 2 + 1] + bias[col + 1] + pr[1];
                *reinterpret_cast<float2*>(&g_emb[(size_t)m * 256 + col]) =
                    make_float2(vx, vy);
            }
        }
    }
}

// ================= kv / out GEMM (BM=64, 2 CTAs/SM) =========================
// BM=64, BN=128, BK=32, 256 threads, warp tile 16x64, K=256.
// acc = 32 regs -> ~110 regs total -> 2 CTAs/SM hides prologue/epilogue.
template <int MODE>
__global__ __launch_bounds__(256, 2) void gemm64(
    const float* __restrict__ Bp, float* __restrict__ Cp,
    const float* __restrict__ bias)
{
    constexpr int K = 256;
    __shared__ __align__(16) uint32_t As[2][64 * 16];
    __shared__ __align__(16) uint32_t Bs[2][128 * 16];

    const int tid   = threadIdx.x;
    const int mBase = blockIdx.y * 64;
    const int nBase = blockIdx.x * 128;

    const int warp = tid >> 5;
    const int lane = tid & 31;
    const int g    = lane >> 2;
    const int tg   = lane & 3;
    const int mw   = (warp & 3) * 16;
    const int nw   = (warp >> 2) * 64;

    const float* A = (MODE == MODE_KV) ? g_emb : g_kv;

    float acc[8][4];
#pragma unroll
    for (int j = 0; j < 8; j++)
#pragma unroll
        for (int l = 0; l < 4; l++) acc[j][l] = 0.0f;

    float4 av[2], bv[4];

    auto load_tile = [&](int kt) {
        const int kbase = kt * 32;
#pragma unroll
        for (int i = 0; i < 2; i++) {
            const int f   = tid + 256 * i;
            const int row = f >> 3;
            const int k4  = f & 7;
            av[i] = *reinterpret_cast<const float4*>(
                A + (size_t)(mBase + row) * K + kbase + k4 * 4);
        }
#pragma unroll
        for (int i = 0; i < 4; i++) {
            const int f   = tid + 256 * i;
            const int row = f >> 3;
            const int k4  = f & 7;
            bv[i] = *reinterpret_cast<const float4*>(
                Bp + (size_t)(nBase + row) * K + kbase + k4 * 4);
        }
    };

    auto store_tile = [&](int s) {
#pragma unroll
        for (int i = 0; i < 2; i++) {
            const int f   = tid + 256 * i;
            const int row = f >> 3;
            const int k4  = f & 7;
            const int wo  = (k4 * 2) ^ ((row & 7) * 2);
            *reinterpret_cast<uint2*>(&As[s][row * 16 + wo]) =
                make_uint2(pack_h2(av[i].x, av[i].y), pack_h2(av[i].z, av[i].w));
        }
#pragma unroll
        for (int i = 0; i < 4; i++) {
            const int f   = tid + 256 * i;
            const int row = f >> 3;
            const int k4  = f & 7;
            const int wo  = (k4 * 2) ^ ((row & 7) * 2);
            *reinterpret_cast<uint2*>(&Bs[s][row * 16 + wo]) =
                make_uint2(pack_h2(bv[i].x, bv[i].y), pack_h2(bv[i].z, bv[i].w));
        }
    };

    auto compute_tile = [&](int s) {
        const int sw = g * 2;
#pragma unroll
        for (int ks = 0; ks < 2; ks++) {
            const int w0 = (ks * 8 + tg) ^ sw;
            const int w2 = (ks * 8 + tg + 4) ^ sw;
            uint32_t a[4], b[8][2];
            {
                const uint32_t* R0 = &As[s][(mw + g) * 16];
                const uint32_t* R8 = R0 + 8 * 16;
                a[0] = R0[w0];  a[1] = R8[w0];
                a[2] = R0[w2];  a[3] = R8[w2];
            }
#pragma unroll
            for (int nt = 0; nt < 8; nt++) {
                const uint32_t* Rn = &Bs[s][(nw + nt * 8 + g) * 16];
                b[nt][0] = Rn[w0];  b[nt][1] = Rn[w2];
            }
#pragma unroll
            for (int nt = 0; nt < 8; nt++)
                mma_f16(acc[nt], a, b[nt]);
        }
    };

    constexpr int NT = K / 32;
    load_tile(0);
    store_tile(0);
    __syncthreads();

    for (int kt = 0; kt < NT; kt++) {
        const int s = kt & 1;
        if (kt + 1 < NT) load_tile(kt + 1);
        compute_tile(s);
        if (kt + 1 < NT) store_tile(1 - s);
        __syncthreads();
    }

    // ---------------- epilogue ----------------
#pragma unroll
    for (int half = 0; half < 2; half++) {
        const int m  = mBase + mw + g + half * 8;
        const int bn = m >> 10, n = m & 1023;
        float kf;
        if (MODE == MODE_KV) {
            const int h = (nBase + nw) >> 6;   // nw multiple of 64
            kf = g_k[(bn * 4 + h) * 1024 + n];
        }
#pragma unroll
        for (int nt = 0; nt < 8; nt++) {
            const int col = nBase + nw + nt * 8 + tg * 2;
            float vx = acc[nt][half * 2 + 0];
            float vy = acc[nt][half * 2 + 1];

            if (MODE == MODE_KV) {
                vx *= kf; vy *= kf;
                *reinterpret_cast<float2*>(&g_kv[(size_t)m * 256 + col]) =
                    make_float2(vx, vy);
            } else {
                vx += bias[col + 0];
                vy += bias[col + 1];
                const int ph = n >> 5, pw = n & 31;
                const int c  = col >> 6;
                const int kh = (col >> 3) & 7;
                const int kw = col & 7;
                const size_t idx =
                    ((((size_t)bn * 64 + c) * 256) + (size_t)(ph * 8 + kh)) * 256
                    + (size_t)(pw * 8 + kw);
                *reinterpret_cast<float2*>(Cp + idx) = make_float2(vx, vy);
            }
        }
    }
}

// ------------------------- small kernels ------------------------------------
__global__ void k_wqavg(const float* __restrict__ Wq)
{
    const int h = blockIdx.x, j = threadIdx.x;
    float s = 0.0f;
#pragma unroll 8
    for (int d = 0; d < 64; d++) s += Wq[(size_t)(h * 64 + d) * 256 + j];
    g_wqavg[h * 256 + j] = s * (1.0f / 64.0f);
}

__global__ __launch_bounds__(256) void k_q2()
{
    __shared__ float wqs[4 * 256];
    const int tid = threadIdx.x;
#pragma unroll
    for (int i = 0; i < 4; i++) wqs[i * 256 + tid] = g_wqavg[i * 256 + tid];
    __syncthreads();

    const int m    = blockIdx.x * 8 + (tid >> 5);
    const int lane = tid & 31;
    const float4* e4 = reinterpret_cast<const float4*>(g_emb + (size_t)m * 256);

    float s[4] = {0.f, 0.f, 0.f, 0.f};
#pragma unroll
    for (int part = 0; part < 2; part++) {
        const float4 ev = e4[lane + part * 32];
        const int base = part * 128 + lane * 4;
#pragma unroll
        for (int h = 0; h < 4; h++) {
            const float4 wv = *reinterpret_cast<const float4*>(&wqs[h * 256 + base]);
            s[h] += ev.x * wv.x + ev.y * wv.y + ev.z * wv.z + ev.w * wv.w;
        }
    }
#pragma unroll
    for (int h = 0; h < 4; h++)
#pragma unroll
        for (int o = 16; o > 0; o >>= 1)
            s[h] += __shfl_xor_sync(0xFFFFFFFFu, s[h], o);

    if (lane == 0) {
        const int bn = m >> 10, n = m & 1023;
#pragma unroll
        for (int h = 0; h < 4; h++)
            g_q[(bn * 4 + h) * 1024 + n] = s[h];
    }
}

__global__ __launch_bounds__(256) void k_sig6(const float* __restrict__ Wk)
{
    const int m    = blockIdx.x * 8 + (threadIdx.x >> 5);
    const int bh0  = blockIdx.y * 4;
    const int lane = threadIdx.x & 31;

    float4 wr[8];
    const float4* wk4 = reinterpret_cast<const float4*>(Wk + (size_t)m * 1024);
#pragma unroll
    for (int j = 0; j < 8; j++) wr[j] = wk4[j * 32 + lane];

    const float4* q0 = reinterpret_cast<const float4*>(g_q + (size_t)(bh0 + 0) * 1024);
    const float4* q1 = reinterpret_cast<const float4*>(g_q + (size_t)(bh0 + 1) * 1024);
    const float4* q2 = reinterpret_cast<const float4*>(g_q + (size_t)(bh0 + 2) * 1024);
    const float4* q3 = reinterpret_cast<const float4*>(g_q + (size_t)(bh0 + 3) * 1024);
    float s0 = 0.f, s1 = 0.f, s2 = 0.f, s3 = 0.f;
#pragma unroll
    for (int j = 0; j < 8; j++) {
        const int idx = j * 32 + lane;
        const float4 a0 = __ldg(&q0[idx]);
        const float4 a1 = __ldg(&q1[idx]);
        const float4 a2 = __ldg(&q2[idx]);
        const float4 a3 = __ldg(&q3[idx]);
        const float4 w = wr[j];
        s0 += a0.x * w.x + a0.y * w.y + a0.z * w.z + a0.w * w.w;
        s1 += a1.x * w.x + a1.y * w.y + a1.z * w.z + a1.w * w.w;
        s2 += a2.x * w.x + a2.y * w.y + a2.z * w.z + a2.w * w.w;
        s3 += a3.x * w.x + a3.y * w.y + a3.z * w.z + a3.w * w.w;
    }
#pragma unroll
    for (int o = 16; o > 0; o >>= 1) {
        s0 += __shfl_xor_sync(0xFFFFFFFFu, s0, o);
        s1 += __shfl_xor_sync(0xFFFFFFFFu, s1, o);
        s2 += __shfl_xor_sync(0xFFFFFFFFu, s2, o);
        s3 += __shfl_xor_sync(0xFFFFFFFFu, s3, o);
    }
    if (lane == 0) {
        g_k[(bh0 + 0) * 1024 + m] = 1.0f / (1.0f + expf(-s0));
        g_k[(bh0 + 1) * 1024 + m] = 1.0f / (1.0f + expf(-s1));
        g_k[(bh0 + 2) * 1024 + m] = 1.0f / (1.0f + expf(-s2));
        g_k[(bh0 + 3) * 1024 + m] = 1.0f / (1.0f + expf(-s3));
    }
}

extern "C" void kernel_launch(void* const* d_in, const int* in_sizes, int n_in,
                              void* d_out, int out_size)
{
    const float* x    = (const float*)d_in[0];
    const float* Wemb = (const float*)d_in[1];
    const float* bemb = (const float*)d_in[2];
    const float* pos  = (const float*)d_in[3];
    const float* Wq   = (const float*)d_in[4];
    const float* Wk   = (const float*)d_in[5];
    const float* Wv   = (const float*)d_in[6];
    const float* Wout = (const float*)d_in[7];
    const float* bout = (const float*)d_in[8];
    float* out = (float*)d_out;

    k_wqavg<<<4, 256>>>(Wq);
    gemm_h<4096><<<dim3(2, 64), 256>>>(x, Wemb, bemb, pos);
    k_q2<<<1024, 256>>>();
    k_sig6<<<dim3(128, 8), 256>>>(Wk);
    gemm64<MODE_KV><<<dim3(2, 128), 256>>>(Wv, nullptr, nullptr);
    gemm64<MODE_OUT><<<dim3(32, 128), 256>>>(Wout, out, bout);
}

// round 11
// speedup vs baseline: 1.1316x; 1.0445x over previous
#include <cuda_runtime.h>
#include <cuda_fp16.h>
#include <math.h>
#include <stdint.h>

// ---------------------------------------------------------------------------
// Vit_Spatial_Map (sm_103 PTX target => legacy mma.sync path).
// FP16 mma.sync m16n8k16, fp32 accumulate.
// B=8, Np=1024, DIM=256, HEADS=4, DH=64, patch_dim=4096, M=8192.
//   emb  = patches @ W_embed^T + b_embed + pos        (8192 x 256, K=4096)
//   q    = emb @ Wq_avg^T (row-mean of Wq per head)   (8192 x 4)
//   k    = sigmoid(q @ Wk^T)                          (32 x 1024)
//   kv   = (emb @ Wv^T) * k                           (8192 x 256, K=256)
//   out  = fold(kv @ Wout^T + b_out)                  (8192 x 4096, K=256)
// All GEMMs: BM=64 x BN=128 x BK=32, 256 thr, 2 CTAs/SM (full 148-SM waves).
// ---------------------------------------------------------------------------

static __device__ float g_emb[8192 * 256];
static __device__ float g_kv[8192 * 256];
static __device__ float g_wqavg[4 * 256];
static __device__ float g_q[32 * 1024];
static __device__ float g_k[32 * 1024];

enum { MODE_EMBED = 0, MODE_KV = 1, MODE_OUT = 2 };

__device__ __forceinline__ uint32_t pack_h2(float x, float y) {
    const __half2 h = __floats2half2_rn(x, y);
    return *reinterpret_cast<const uint32_t*>(&h);
}
__device__ __forceinline__ void mma_f16(float* c, const uint32_t* a, const uint32_t* b) {
    asm volatile(
        "mma.sync.aligned.m16n8k16.row.col.f32.f16.f16.f32 "
        "{%0,%1,%2,%3}, {%4,%5,%6,%7}, {%8,%9}, {%0,%1,%2,%3};"
        : "+f"(c[0]), "+f"(c[1]), "+f"(c[2]), "+f"(c[3])
        : "r"(a[0]), "r"(a[1]), "r"(a[2]), "r"(a[3]), "r"(b[0]), "r"(b[1]));
}

// C(M x N) = A(M x K) * B(N x K)^T. BM=64, BN=128, BK=32, 256 threads.
// Warp grid 4(m) x 2(n); warp tile 16 x 64; acc 32 regs -> 2 CTAs/SM.
// SMEM halves [row][16 words], XOR swizzle word ^= (row&7)*2 (conflict-free).
template <int MODE, int K>
__global__ __launch_bounds__(256, 2) void gemm64(
    const float* __restrict__ Ap, const float* __restrict__ Bp,
    float* __restrict__ Cp, const float* __restrict__ bias,
    const float* __restrict__ pos)
{
    __shared__ __align__(16) uint32_t As[2][64 * 16];
    __shared__ __align__(16) uint32_t Bs[2][128 * 16];

    const int tid   = threadIdx.x;
    const int mBase = blockIdx.y * 64;
    const int nBase = blockIdx.x * 128;

    const int warp = tid >> 5;
    const int lane = tid & 31;
    const int g    = lane >> 2;
    const int tg   = lane & 3;
    const int mw   = (warp & 3) * 16;
    const int nw   = (warp >> 2) * 64;

    const float* A = (MODE == MODE_EMBED) ? Ap : (MODE == MODE_KV ? g_emb : g_kv);

    float acc[8][4];
#pragma unroll
    for (int j = 0; j < 8; j++)
#pragma unroll
        for (int l = 0; l < 4; l++) acc[j][l] = 0.0f;

    float4 av[2], bv[4];

    auto load_tile = [&](int kt) {
        const int kbase = kt * 32;
#pragma unroll
        for (int i = 0; i < 2; i++) {
            const int f   = tid + 256 * i;
            const int row = f >> 3;
            const int k4  = f & 7;
            const int ka  = kbase + k4 * 4;
            if (MODE == MODE_EMBED) {
                const int c  = ka >> 6;
                const int kh = (ka >> 3) & 7;
                const int kw = ka & 7;
                const int m  = mBase + row;
                const int bn = m >> 10, n = m & 1023;
                const int ph = n >> 5, pw = n & 31;
                const size_t idx =
                    ((((size_t)bn * 64 + c) * 256) + (size_t)(ph * 8 + kh)) * 256
                    + (size_t)(pw * 8 + kw);
                av[i] = *reinterpret_cast<const float4*>(A + idx);
            } else {
                av[i] = *reinterpret_cast<const float4*>(
                    A + (size_t)(mBase + row) * K + ka);
            }
        }
#pragma unroll
        for (int i = 0; i < 4; i++) {
            const int f   = tid + 256 * i;
            const int row = f >> 3;
            const int k4  = f & 7;
            bv[i] = *reinterpret_cast<const float4*>(
                Bp + (size_t)(nBase + row) * K + kbase + k4 * 4);
        }
    };

    auto store_tile = [&](int s) {
#pragma unroll
        for (int i = 0; i < 2; i++) {
            const int f   = tid + 256 * i;
            const int row = f >> 3;
            const int k4  = f & 7;
            const int wo  = (k4 * 2) ^ ((row & 7) * 2);
            *reinterpret_cast<uint2*>(&As[s][row * 16 + wo]) =
                make_uint2(pack_h2(av[i].x, av[i].y), pack_h2(av[i].z, av[i].w));
        }
#pragma unroll
        for (int i = 0; i < 4; i++) {
            const int f   = tid + 256 * i;
            const int row = f >> 3;
            const int k4  = f & 7;
            const int wo  = (k4 * 2) ^ ((row & 7) * 2);
            *reinterpret_cast<uint2*>(&Bs[s][row * 16 + wo]) =
                make_uint2(pack_h2(bv[i].x, bv[i].y), pack_h2(bv[i].z, bv[i].w));
        }
    };

    auto compute_tile = [&](int s) {
        const int sw = g * 2;
#pragma unroll
        for (int ks = 0; ks < 2; ks++) {
            const int w0 = (ks * 8 + tg) ^ sw;
            const int w2 = (ks * 8 + tg + 4) ^ sw;
            uint32_t a[4], b[8][2];
            {
                const uint32_t* R0 = &As[s][(mw + g) * 16];
                const uint32_t* R8 = R0 + 8 * 16;
                a[0] = R0[w0];  a[1] = R8[w0];
                a[2] = R0[w2];  a[3] = R8[w2];
            }
#pragma unroll
            for (int nt = 0; nt < 8; nt++) {
                const uint32_t* Rn = &Bs[s][(nw + nt * 8 + g) * 16];
                b[nt][0] = Rn[w0];  b[nt][1] = Rn[w2];
            }
#pragma unroll
            for (int nt = 0; nt < 8; nt++)
                mma_f16(acc[nt], a, b[nt]);
        }
    };

    constexpr int NT = K / 32;
    load_tile(0);
    store_tile(0);
    __syncthreads();

    for (int kt = 0; kt < NT; kt++) {
        const int s = kt & 1;
        if (kt + 1 < NT) load_tile(kt + 1);
        compute_tile(s);
        if (kt + 1 < NT) store_tile(1 - s);
        __syncthreads();
    }

    // ---------------- epilogue ----------------
#pragma unroll
    for (int half = 0; half < 2; half++) {
        const int m  = mBase + mw + g + half * 8;
        const int bn = m >> 10, n = m & 1023;
        float kf;
        if (MODE == MODE_KV) {
            const int h = (nBase + nw) >> 6;   // nw multiple of 64
            kf = g_k[(bn * 4 + h) * 1024 + n];
        }
#pragma unroll
        for (int nt = 0; nt < 8; nt++) {
            const int col = nBase + nw + nt * 8 + tg * 2;
            float vx = acc[nt][half * 2 + 0];
            float vy = acc[nt][half * 2 + 1];

            if (MODE == MODE_EMBED) {
                const float* pr = pos + (size_t)n * 256 + col;
                vx += bias[col + 0] + pr[0];
                vy += bias[col + 1] + pr[1];
                *reinterpret_cast<float2*>(&g_emb[(size_t)m * 256 + col]) =
                    make_float2(vx, vy);
            } else if (MODE == MODE_KV) {
                vx *= kf; vy *= kf;
                *reinterpret_cast<float2*>(&g_kv[(size_t)m * 256 + col]) =
                    make_float2(vx, vy);
            } else {
                vx += bias[col + 0];
                vy += bias[col + 1];
                const int ph = n >> 5, pw = n & 31;
                const int c  = col >> 6;
                const int kh = (col >> 3) & 7;
                const int kw = col & 7;
                const size_t idx =
                    ((((size_t)bn * 64 + c) * 256) + (size_t)(ph * 8 + kh)) * 256
                    + (size_t)(pw * 8 + kw);
                *reinterpret_cast<float2*>(Cp + idx) = make_float2(vx, vy);
            }
        }
    }
}

// ------------------------- small kernels ------------------------------------
__global__ void k_wqavg(const float* __restrict__ Wq)
{
    const int h = blockIdx.x, j = threadIdx.x;
    float s = 0.0f;
#pragma unroll 8
    for (int d = 0; d < 64; d++) s += Wq[(size_t)(h * 64 + d) * 256 + j];
    g_wqavg[h * 256 + j] = s * (1.0f / 64.0f);
}

__global__ __launch_bounds__(256) void k_q2()
{
    __shared__ float wqs[4 * 256];
    const int tid = threadIdx.x;
#pragma unroll
    for (int i = 0; i < 4; i++) wqs[i * 256 + tid] = g_wqavg[i * 256 + tid];
    __syncthreads();

    const int m    = blockIdx.x * 8 + (tid >> 5);
    const int lane = tid & 31;
    const float4* e4 = reinterpret_cast<const float4*>(g_emb + (size_t)m * 256);

    float s[4] = {0.f, 0.f, 0.f, 0.f};
#pragma unroll
    for (int part = 0; part < 2; part++) {
        const float4 ev = e4[lane + part * 32];
        const int base = part * 128 + lane * 4;
#pragma unroll
        for (int h = 0; h < 4; h++) {
            const float4 wv = *reinterpret_cast<const float4*>(&wqs[h * 256 + base]);
            s[h] += ev.x * wv.x + ev.y * wv.y + ev.z * wv.z + ev.w * wv.w;
        }
    }
#pragma unroll
    for (int h = 0; h < 4; h++)
#pragma unroll
        for (int o = 16; o > 0; o >>= 1)
            s[h] += __shfl_xor_sync(0xFFFFFFFFu, s[h], o);

    if (lane == 0) {
        const int bn = m >> 10, n = m & 1023;
#pragma unroll
        for (int h = 0; h < 4; h++)
            g_q[(bn * 4 + h) * 1024 + n] = s[h];
    }
}

__global__ __launch_bounds__(256) void k_sig6(const float* __restrict__ Wk)
{
    const int m    = blockIdx.x * 8 + (threadIdx.x >> 5);
    const int bh0  = blockIdx.y * 4;
    const int lane = threadIdx.x & 31;

    float4 wr[8];
    const float4* wk4 = reinterpret_cast<const float4*>(Wk + (size_t)m * 1024);
#pragma unroll
    for (int j = 0; j < 8; j++) wr[j] = wk4[j * 32 + lane];

    const float4* q0 = reinterpret_cast<const float4*>(g_q + (size_t)(bh0 + 0) * 1024);
    const float4* q1 = reinterpret_cast<const float4*>(g_q + (size_t)(bh0 + 1) * 1024);
    const float4* q2 = reinterpret_cast<const float4*>(g_q + (size_t)(bh0 + 2) * 1024);
    const float4* q3 = reinterpret_cast<const float4*>(g_q + (size_t)(bh0 + 3) * 1024);
    float s0 = 0.f, s1 = 0.f, s2 = 0.f, s3 = 0.f;
#pragma unroll
    for (int j = 0; j < 8; j++) {
        const int idx = j * 32 + lane;
        const float4 a0 = __ldg(&q0[idx]);
        const float4 a1 = __ldg(&q1[idx]);
        const float4 a2 = __ldg(&q2[idx]);
        const float4 a3 = __ldg(&q3[idx]);
        const float4 w = wr[j];
        s0 += a0.x * w.x + a0.y * w.y + a0.z * w.z + a0.w * w.w;
        s1 += a1.x * w.x + a1.y * w.y + a1.z * w.z + a1.w * w.w;
        s2 += a2.x * w.x + a2.y * w.y + a2.z * w.z + a2.w * w.w;
        s3 += a3.x * w.x + a3.y * w.y + a3.z * w.z + a3.w * w.w;
    }
#pragma unroll
    for (int o = 16; o > 0; o >>= 1) {
        s0 += __shfl_xor_sync(0xFFFFFFFFu, s0, o);
        s1 += __shfl_xor_sync(0xFFFFFFFFu, s1, o);
        s2 += __shfl_xor_sync(0xFFFFFFFFu, s2, o);
        s3 += __shfl_xor_sync(0xFFFFFFFFu, s3, o);
    }
    if (lane == 0) {
        g_k[(bh0 + 0) * 1024 + m] = 1.0f / (1.0f + expf(-s0));
        g_k[(bh0 + 1) * 1024 + m] = 1.0f / (1.0f + expf(-s1));
        g_k[(bh0 + 2) * 1024 + m] = 1.0f / (1.0f + expf(-s2));
        g_k[(bh0 + 3) * 1024 + m] = 1.0f / (1.0f + expf(-s3));
    }
}

extern "C" void kernel_launch(void* const* d_in, const int* in_sizes, int n_in,
                              void* d_out, int out_size)
{
    const float* x    = (const float*)d_in[0];
    const float* Wemb = (const float*)d_in[1];
    const float* bemb = (const float*)d_in[2];
    const float* pos  = (const float*)d_in[3];
    const float* Wq   = (const float*)d_in[4];
    const float* Wk   = (const float*)d_in[5];
    const float* Wv   = (const float*)d_in[6];
    const float* Wout = (const float*)d_in[7];
    const float* bout = (const float*)d_in[8];
    float* out = (float*)d_out;

    k_wqavg<<<4, 256>>>(Wq);
    gemm64<MODE_EMBED, 4096><<<dim3(2, 128), 256>>>(x, Wemb, nullptr, bemb, pos);
    k_q2<<<1024, 256>>>();
    k_sig6<<<dim3(128, 8), 256>>>(Wk);
    gemm64<MODE_KV, 256><<<dim3(2, 128), 256>>>(nullptr, Wv, nullptr, nullptr, nullptr);
    gemm64<MODE_OUT, 256><<<dim3(32, 128), 256>>>(nullptr, Wout, out, bout, nullptr);
}

// round 12
// speedup vs baseline: 1.1330x; 1.0013x over previous
#include <cuda_runtime.h>
#include <cuda_fp16.h>
#include <math.h>
#include <stdint.h>

// ---------------------------------------------------------------------------
// Vit_Spatial_Map (sm_103 PTX target => legacy mma.sync path).
// FP16 mma.sync m16n8k16, fp32 accumulate.
// B=8, Np=1024, DIM=256, HEADS=4, DH=64, patch_dim=4096, M=8192.
//   emb  = patches @ W_embed^T + b_embed + pos        (8192 x 256, K=4096)
//   q    = emb @ Wq_avg^T (row-mean of Wq per head)   (8192 x 4)
//   k    = sigmoid(q @ Wk^T)      — fused as phase-0 of the kv GEMM
//   kv   = (emb @ Wv^T) * k                           (8192 x 256, K=256)
//   out  = fold(kv @ Wout^T + b_out)                  (8192 x 4096, K=256)
// All GEMMs: BM=64 x BN=128 x BK=32, 256 thr, 2 CTAs/SM.
// ---------------------------------------------------------------------------

static __device__ float g_emb[8192 * 256];
static __device__ float g_kv[8192 * 256];
static __device__ float g_wqavg[4 * 256];
static __device__ float g_q[32 * 1024];

enum { MODE_EMBED = 0, MODE_KV = 1, MODE_OUT = 2 };

__device__ __forceinline__ uint32_t pack_h2(float x, float y) {
    const __half2 h = __floats2half2_rn(x, y);
    return *reinterpret_cast<const uint32_t*>(&h);
}
__device__ __forceinline__ void mma_f16(float* c, const uint32_t* a, const uint32_t* b) {
    asm volatile(
        "mma.sync.aligned.m16n8k16.row.col.f32.f16.f16.f32 "
        "{%0,%1,%2,%3}, {%4,%5,%6,%7}, {%8,%9}, {%0,%1,%2,%3};"
        : "+f"(c[0]), "+f"(c[1]), "+f"(c[2]), "+f"(c[3])
        : "r"(a[0]), "r"(a[1]), "r"(a[2]), "r"(a[3]), "r"(b[0]), "r"(b[1]));
}

// C(M x N) = A(M x K) * B(N x K)^T. BM=64, BN=128, BK=32, 256 threads.
// Warp grid 4(m) x 2(n); warp tile 16 x 64; acc 32 regs -> 2 CTAs/SM.
// MODE_KV: phase-0 computes this CTA's 128 k=sigmoid(q.Wk) values into smem.
template <int MODE, int K>
__global__ __launch_bounds__(256, 2) void gemm64(
    const float* __restrict__ Ap, const float* __restrict__ Bp,
    float* __restrict__ Cp, const float* __restrict__ bias,
    const float* __restrict__ pos, const float* __restrict__ Wk)
{
    __shared__ __align__(16) uint32_t As[2][64 * 16];
    __shared__ __align__(16) uint32_t Bs[2][128 * 16];
    __shared__ float ksm[128];   // MODE_KV: [head_local*64 + n_local]

    const int tid   = threadIdx.x;
    const int mBase = blockIdx.y * 64;
    const int nBase = blockIdx.x * 128;

    const int warp = tid >> 5;
    const int lane = tid & 31;
    const int g    = lane >> 2;
    const int tg   = lane & 3;
    const int mw   = (warp & 3) * 16;
    const int nw   = (warp >> 2) * 64;

    const float* A = (MODE == MODE_EMBED) ? Ap : (MODE == MODE_KV ? g_emb : g_kv);

    // ---- phase 0 (KV only): k = sigmoid(q . Wk-row) for this CTA's block ----
    if (MODE == MODE_KV) {
        const int bn = mBase >> 10;
        const int n0 = mBase & 1023;
        const int h0 = nBase >> 6;
#pragma unroll
        for (int r = 0; r < 4; r++) {
            const int vbase = warp * 16 + r * 4;
            const float4* wrow[4];
            const float4* qrow[4];
#pragma unroll
            for (int u = 0; u < 4; u++) {
                const int v = vbase + u;
                wrow[u] = reinterpret_cast<const float4*>(
                    Wk + (size_t)(n0 + (v & 63)) * 1024);
                qrow[u] = reinterpret_cast<const float4*>(
                    g_q + (size_t)(bn * 4 + h0 + (v >> 6)) * 1024);
            }
            float s[4] = {0.f, 0.f, 0.f, 0.f};
#pragma unroll
            for (int j = 0; j < 8; j++) {
                const int idx = j * 32 + lane;
#pragma unroll
                for (int u = 0; u < 4; u++) {
                    const float4 a = __ldg(&qrow[u][idx]);
                    const float4 b = __ldg(&wrow[u][idx]);
                    s[u] += a.x * b.x + a.y * b.y + a.z * b.z + a.w * b.w;
                }
            }
#pragma unroll
            for (int u = 0; u < 4; u++)
#pragma unroll
                for (int o = 16; o > 0; o >>= 1)
                    s[u] += __shfl_xor_sync(0xFFFFFFFFu, s[u], o);
            if (lane == 0) {
#pragma unroll
                for (int u = 0; u < 4; u++)
                    ksm[vbase + u] = 1.0f / (1.0f + expf(-s[u]));
            }
        }
        // visibility to other warps guaranteed by the main-loop __syncthreads
    }

    float acc[8][4];
#pragma unroll
    for (int j = 0; j < 8; j++)
#pragma unroll
        for (int l = 0; l < 4; l++) acc[j][l] = 0.0f;

    float4 av[2], bv[4];

    auto load_tile = [&](int kt) {
        const int kbase = kt * 32;
#pragma unroll
        for (int i = 0; i < 2; i++) {
            const int f   = tid + 256 * i;
            const int row = f >> 3;
            const int k4  = f & 7;
            const int ka  = kbase + k4 * 4;
            if (MODE == MODE_EMBED) {
                const int c  = ka >> 6;
                const int kh = (ka >> 3) & 7;
                const int kw = ka & 7;
                const int m  = mBase + row;
                const int bn = m >> 10, n = m & 1023;
                const int ph = n >> 5, pw = n & 31;
                const size_t idx =
                    ((((size_t)bn * 64 + c) * 256) + (size_t)(ph * 8 + kh)) * 256
                    + (size_t)(pw * 8 + kw);
                av[i] = *reinterpret_cast<const float4*>(A + idx);
            } else {
                av[i] = *reinterpret_cast<const float4*>(
                    A + (size_t)(mBase + row) * K + ka);
            }
        }
#pragma unroll
        for (int i = 0; i < 4; i++) {
            const int f   = tid + 256 * i;
            const int row = f >> 3;
            const int k4  = f & 7;
            bv[i] = *reinterpret_cast<const float4*>(
                Bp + (size_t)(nBase + row) * K + kbase + k4 * 4);
        }
    };

    auto store_tile = [&](int s) {
#pragma unroll
        for (int i = 0; i < 2; i++) {
            const int f   = tid + 256 * i;
            const int row = f >> 3;
            const int k4  = f & 7;
            const int wo  = (k4 * 2) ^ ((row & 7) * 2);
            *reinterpret_cast<uint2*>(&As[s][row * 16 + wo]) =
                make_uint2(pack_h2(av[i].x, av[i].y), pack_h2(av[i].z, av[i].w));
        }
#pragma unroll
        for (int i = 0; i < 4; i++) {
            const int f   = tid + 256 * i;
            const int row = f >> 3;
            const int k4  = f & 7;
            const int wo  = (k4 * 2) ^ ((row & 7) * 2);
            *reinterpret_cast<uint2*>(&Bs[s][row * 16 + wo]) =
                make_uint2(pack_h2(bv[i].x, bv[i].y), pack_h2(bv[i].z, bv[i].w));
        }
    };

    auto compute_tile = [&](int s) {
        const int sw = g * 2;
#pragma unroll
        for (int ks = 0; ks < 2; ks++) {
            const int w0 = (ks * 8 + tg) ^ sw;
            const int w2 = (ks * 8 + tg + 4) ^ sw;
            uint32_t a[4], b[8][2];
            {
                const uint32_t* R0 = &As[s][(mw + g) * 16];
                const uint32_t* R8 = R0 + 8 * 16;
                a[0] = R0[w0];  a[1] = R8[w0];
                a[2] = R0[w2];  a[3] = R8[w2];
            }
#pragma unroll
            for (int nt = 0; nt < 8; nt++) {
                const uint32_t* Rn = &Bs[s][(nw + nt * 8 + g) * 16];
                b[nt][0] = Rn[w0];  b[nt][1] = Rn[w2];
            }
#pragma unroll
            for (int nt = 0; nt < 8; nt++)
                mma_f16(acc[nt], a, b[nt]);
        }
    };

    constexpr int NT = K / 32;
    load_tile(0);
    store_tile(0);
    __syncthreads();

    for (int kt = 0; kt < NT; kt++) {
        const int s = kt & 1;
        if (kt + 1 < NT) load_tile(kt + 1);
        compute_tile(s);
        if (kt + 1 < NT) store_tile(1 - s);
        __syncthreads();
    }

    // ---------------- epilogue ----------------
#pragma unroll
    for (int half = 0; half < 2; half++) {
        const int m  = mBase + mw + g + half * 8;
        const int bn = m >> 10, n = m & 1023;
        float kf;
        if (MODE == MODE_KV)
            kf = ksm[(nw >> 6) * 64 + (m & 63)];
#pragma unroll
        for (int nt = 0; nt < 8; nt++) {
            const int col = nBase + nw + nt * 8 + tg * 2;
            float vx = acc[nt][half * 2 + 0];
            float vy = acc[nt][half * 2 + 1];

            if (MODE == MODE_EMBED) {
                const float* pr = pos + (size_t)n * 256 + col;
                vx += bias[col + 0] + pr[0];
                vy += bias[col + 1] + pr[1];
                *reinterpret_cast<float2*>(&g_emb[(size_t)m * 256 + col]) =
                    make_float2(vx, vy);
            } else if (MODE == MODE_KV) {
                vx *= kf; vy *= kf;
                *reinterpret_cast<float2*>(&g_kv[(size_t)m * 256 + col]) =
                    make_float2(vx, vy);
            } else {
                vx += bias[col + 0];
                vy += bias[col + 1];
                const int ph = n >> 5, pw = n & 31;
                const int c  = col >> 6;
                const int kh = (col >> 3) & 7;
                const int kw = col & 7;
                const size_t idx =
                    ((((size_t)bn * 64 + c) * 256) + (size_t)(ph * 8 + kh)) * 256
                    + (size_t)(pw * 8 + kw);
                *reinterpret_cast<float2*>(Cp + idx) = make_float2(vx, vy);
            }
        }
    }
}

// ------------------------- small kernels ------------------------------------
__global__ void k_wqavg(const float* __restrict__ Wq)
{
    const int h = blockIdx.x, j = threadIdx.x;
    float s = 0.0f;
#pragma unroll 8
    for (int d = 0; d < 64; d++) s += Wq[(size_t)(h * 64 + d) * 256 + j];
    g_wqavg[h * 256 + j] = s * (1.0f / 64.0f);
}

__global__ __launch_bounds__(256) void k_q2()
{
    __shared__ float wqs[4 * 256];
    const int tid = threadIdx.x;
#pragma unroll
    for (int i = 0; i < 4; i++) wqs[i * 256 + tid] = g_wqavg[i * 256 + tid];
    __syncthreads();

    const int m    = blockIdx.x * 8 + (tid >> 5);
    const int lane = tid & 31;
    const float4* e4 = reinterpret_cast<const float4*>(g_emb + (size_t)m * 256);

    float s[4] = {0.f, 0.f, 0.f, 0.f};
#pragma unroll
    for (int part = 0; part < 2; part++) {
        const float4 ev = e4[lane + part * 32];
        const int base = part * 128 + lane * 4;
#pragma unroll
        for (int h = 0; h < 4; h++) {
            const float4 wv = *reinterpret_cast<const float4*>(&wqs[h * 256 + base]);
            s[h] += ev.x * wv.x + ev.y * wv.y + ev.z * wv.z + ev.w * wv.w;
        }
    }
#pragma unroll
    for (int h = 0; h < 4; h++)
#pragma unroll
        for (int o = 16; o > 0; o >>= 1)
            s[h] += __shfl_xor_sync(0xFFFFFFFFu, s[h], o);

    if (lane == 0) {
        const int bn = m >> 10, n = m & 1023;
#pragma unroll
        for (int h = 0; h < 4; h++)
            g_q[(bn * 4 + h) * 1024 + n] = s[h];
    }
}

extern "C" void kernel_launch(void* const* d_in, const int* in_sizes, int n_in,
                              void* d_out, int out_size)
{
    const float* x    = (const float*)d_in[0];
    const float* Wemb = (const float*)d_in[1];
    const float* bemb = (const float*)d_in[2];
    const float* pos  = (const float*)d_in[3];
    const float* Wq   = (const float*)d_in[4];
    const float* Wk   = (const float*)d_in[5];
    const float* Wv   = (const float*)d_in[6];
    const float* Wout = (const float*)d_in[7];
    const float* bout = (const float*)d_in[8];
    float* out = (float*)d_out;

    k_wqavg<<<4, 256>>>(Wq);
    gemm64<MODE_EMBED, 4096><<<dim3(2, 128), 256>>>(
        x, Wemb, nullptr, bemb, pos, nullptr);
    k_q2<<<1024, 256>>>();
    gemm64<MODE_KV, 256><<<dim3(2, 128), 256>>>(
        nullptr, Wv, nullptr, nullptr, nullptr, Wk);
    gemm64<MODE_OUT, 256><<<dim3(32, 128), 256>>>(
        nullptr, Wout, out, bout, nullptr, nullptr);
}